// round 10
// baseline (speedup 1.0000x reference)
#include <cuda_runtime.h>
#include <math.h>

#define B 32
#define S 4096
#define H 1024
#define WARPS_PER_BLOCK 8
#define K1_THREADS (WARPS_PER_BLOCK * 32)      // 256
#define K1_BLOCKS 296                          // 2 blocks/SM on 148 SMs
#define NWARPS (K1_BLOCKS * WARPS_PER_BLOCK)   // 2368
#define WARPS_PER_BATCH (NWARPS / B)           // 74
#define ROWS_BASE (S / WARPS_PER_BATCH)        // 55
#define ROWS_REM (S % WARPS_PER_BATCH)         // 26 (first 26 warps do 56 rows)

// Scratch (__device__ globals; no dynamic allocation allowed)
__device__ float4 g_ctx_partial[NWARPS * (H / 4)];   // 9.5 MB, batch-contiguous
__device__ float  g_m_partial[NWARPS];
__device__ float  g_l_partial[NWARPS];

// ---------------------------------------------------------------------------
// Kernel 1: single streaming pass over keys (proven 82.5us).
// b = wg / 74, slot i = wg % 74; q, kv, acc all in registers; 2 blocks/SM.
// ---------------------------------------------------------------------------
__global__ __launch_bounds__(K1_THREADS)
void k1_scores_partial_ctx(const float* __restrict__ query,
                           const float* __restrict__ keys,
                           float* __restrict__ out_weights /* raw scores */)
{
    const int wg   = blockIdx.x * WARPS_PER_BLOCK + (threadIdx.x >> 5);
    const int lane = threadIdx.x & 31;
    const int b    = wg / WARPS_PER_BATCH;
    const int i    = wg % WARPS_PER_BATCH;
    const int start = i * ROWS_BASE + (i < ROWS_REM ? i : ROWS_REM);
    const int count = ROWS_BASE + (i < ROWS_REM ? 1 : 0);

    const float4* q4 = reinterpret_cast<const float4*>(query + (size_t)b * H);
    float4 qv[8];
#pragma unroll
    for (int j = 0; j < 8; ++j) qv[j] = q4[lane + 32 * j];

    float4 acc[8];
#pragma unroll
    for (int j = 0; j < 8; ++j) acc[j] = make_float4(0.f, 0.f, 0.f, 0.f);
    float m = -INFINITY;
    float l = 0.f;

    const size_t base = ((size_t)b * S + start) * H;
    float* wout = out_weights + (size_t)b * S + start;

    for (int r = 0; r < count; ++r) {
        const float4* k4 = reinterpret_cast<const float4*>(keys + base + (size_t)r * H);
        float4 kv[8];
#pragma unroll
        for (int j = 0; j < 8; ++j) kv[j] = k4[lane + 32 * j];

        float d = 0.f;
#pragma unroll
        for (int j = 0; j < 8; ++j) {
            d = fmaf(qv[j].x, kv[j].x, d);
            d = fmaf(qv[j].y, kv[j].y, d);
            d = fmaf(qv[j].z, kv[j].z, d);
            d = fmaf(qv[j].w, kv[j].w, d);
        }
#pragma unroll
        for (int o = 16; o > 0; o >>= 1)
            d += __shfl_xor_sync(0xFFFFFFFFu, d, o);

        if (lane == 0) wout[r] = d;

        float p;
        if (d > m) {                       // warp-uniform branch
            float scale = __expf(m - d);   // first iter: exp(-inf)=0
#pragma unroll
            for (int j = 0; j < 8; ++j) {
                acc[j].x *= scale; acc[j].y *= scale;
                acc[j].z *= scale; acc[j].w *= scale;
            }
            l = fmaf(l, scale, 1.f);
            m = d;
            p = 1.f;
        } else {
            p = __expf(d - m);
            l += p;
        }
#pragma unroll
        for (int j = 0; j < 8; ++j) {
            acc[j].x = fmaf(p, kv[j].x, acc[j].x);
            acc[j].y = fmaf(p, kv[j].y, acc[j].y);
            acc[j].z = fmaf(p, kv[j].z, acc[j].z);
            acc[j].w = fmaf(p, kv[j].w, acc[j].w);
        }
    }

    float4* dst = &g_ctx_partial[(size_t)wg * (H / 4)];
#pragma unroll
    for (int j = 0; j < 8; ++j) dst[lane + 32 * j] = acc[j];
    if (lane == 0) {
        g_m_partial[wg] = m;
        g_l_partial[wg] = l;
    }
}

// ---------------------------------------------------------------------------
// Kernel 2 (single fused finalize, 384 blocks, no cross-block deps):
// Every block redundantly reduces its batch's 74 (m,l) pairs (L2-resident,
// ~600B) to get M and 1/L. Then:
//   blocks 0..127   : normalize 256 float4 of weights each (4 blocks/batch)
//   blocks 128..383 : 8 blocks/batch; block `sub` produces H-slice
//                     [sub*128, sub*128+128) of the context by summing all
//                     74 partials over that slice. Direct store, no atomics.
// ---------------------------------------------------------------------------
#define K2_THREADS 256
#define WNORM_BLOCKS ((B * S / 4) / K2_THREADS)   // 128
#define CSLICE_BLOCKS_PER_BATCH 8                 // 128 floats of H each
#define K2_BLOCKS (WNORM_BLOCKS + B * CSLICE_BLOCKS_PER_BATCH)  // 384

__global__ __launch_bounds__(K2_THREADS)
void k2_fused_finalize(float* __restrict__ out_ctx, float* __restrict__ out_weights)
{
    const int bid = blockIdx.x;
    const int t   = threadIdx.x;
    const bool is_norm = (bid < WNORM_BLOCKS);
    const int b = is_norm ? (bid >> 2) : ((bid - WNORM_BLOCKS) >> 3);

    // --- redundant per-block stats over this batch's 74 (m,l) pairs ---
    __shared__ float sm[4], sl[4];
    __shared__ float sM, sInvL;

    float mc = -INFINITY, lc = 0.f;
    if (t < WARPS_PER_BATCH) {
        const int p = b * WARPS_PER_BATCH + t;
        mc = g_m_partial[p];
        lc = g_l_partial[p];
    }
    if (t < 128) {
        float v = mc;
#pragma unroll
        for (int o = 16; o > 0; o >>= 1)
            v = fmaxf(v, __shfl_xor_sync(0xFFFFFFFFu, v, o));
        if ((t & 31) == 0) sm[t >> 5] = v;
    }
    __syncthreads();
    if (t == 0) sM = fmaxf(fmaxf(sm[0], sm[1]), fmaxf(sm[2], sm[3]));
    __syncthreads();
    const float M = sM;
    if (t < 128) {
        float s = lc * __expf(mc - M);   // idle slots contribute 0
#pragma unroll
        for (int o = 16; o > 0; o >>= 1)
            s += __shfl_xor_sync(0xFFFFFFFFu, s, o);
        if ((t & 31) == 0) sl[t >> 5] = s;
    }
    __syncthreads();
    if (t == 0) sInvL = 1.f / (sl[0] + sl[1] + sl[2] + sl[3]);
    __syncthreads();
    const float invL = sInvL;

    if (is_norm) {
        // normalize weights: block covers 256 contiguous float4 of batch b
        const int idx = bid * K2_THREADS + t;   // global float4 idx; bid>>2 == b
        float4 s = reinterpret_cast<float4*>(out_weights)[idx];
        s.x = __expf(s.x - M) * invL;
        s.y = __expf(s.y - M) * invL;
        s.z = __expf(s.z - M) * invL;
        s.w = __expf(s.w - M) * invL;
        reinterpret_cast<float4*>(out_weights)[idx] = s;
    } else {
        const int sub = (bid - WNORM_BLOCKS) & (CSLICE_BLOCKS_PER_BATCH - 1);
        // thread t: slot-group = t>>5 (0..7), float4 within slice = t&31
        const int f = t & 31;
        float4 a = make_float4(0.f, 0.f, 0.f, 0.f);
        for (int i = (t >> 5); i < WARPS_PER_BATCH; i += 8) {
            const int p = b * WARPS_PER_BATCH + i;
            const float fct = __expf(g_m_partial[p] - M) * invL;
            float4 v = g_ctx_partial[(size_t)p * (H / 4) + sub * 32 + f];
            a.x = fmaf(fct, v.x, a.x);
            a.y = fmaf(fct, v.y, a.y);
            a.z = fmaf(fct, v.z, a.z);
            a.w = fmaf(fct, v.w, a.w);
        }
        __shared__ float4 sacc[8][32];   // 4 KB
        sacc[t >> 5][f] = a;
        __syncthreads();
        if (t < 32) {
            float4 c = sacc[0][t];
#pragma unroll
            for (int g = 1; g < 8; ++g) {
                float4 v = sacc[g][t];
                c.x += v.x; c.y += v.y; c.z += v.z; c.w += v.w;
            }
            reinterpret_cast<float4*>(out_ctx)[b * (H / 4) + sub * 32 + t] = c;
        }
    }
}

extern "C" void kernel_launch(void* const* d_in, const int* in_sizes, int n_in,
                              void* d_out, int out_size)
{
    const float* query = (const float*)d_in[0];   // (32,1,1024)
    const float* keys  = (const float*)d_in[1];   // (32,4096,1024)
    float* out = (float*)d_out;
    float* out_ctx = out;                  // (B,H)
    float* out_w   = out + (size_t)B * H;  // (B,S)

    k1_scores_partial_ctx<<<K1_BLOCKS, K1_THREADS>>>(query, keys, out_w);
    k2_fused_finalize<<<K2_BLOCKS, K2_THREADS>>>(out_ctx, out_w);
}